// round 12
// baseline (speedup 1.0000x reference)
#include <cuda_runtime.h>
#include <cuda_bf16.h>
#include <math.h>

// ---------------- static problem sizes ----------------
#define N_TREES 128
#define DEPTH   10
#define NODES_PER_TREE 1023      // 2^10 - 1
#define NC 16                    // C states
#define NM 256                   // M symbols
#define NL 2                     // child positions
#define NG 8                     // generators

typedef unsigned long long ull;
union U2 { ull u; float2 f; };
union F4 { float4 f; ull u[2]; };

// ---------------- normalized parameters (device globals, no alloc) ----------
// g_An[g][l][b][a] = softmax_a(lambda_A[a,b,l,g]) * SP[l,g]   (SP folded in)
// g_Bn[g][m][c]    = softmax_m(lambda_B[c,m,g])
// g_Pin[g][l][c]   = softmax_c(lambda_Pi[c,l,g])
// g_S [g][l][m]    = sum_c Pi[c,l,g]*B[c,m,g]   (leaf normalizer table)
__device__ float g_An [NG][NL][NC][NC];
__device__ float g_Bn [NG][NM][NC];
__device__ float g_Pin[NG][NL][NC];
__device__ float g_S  [NG][NL][NM];

// ---------------- packed f32x2 helpers (sm_103a FFMA2) ----------------
__device__ __forceinline__ ull ffma2(ull a, ull b, ull c) {
    ull d;
    asm("fma.rn.f32x2 %0, %1, %2, %3;" : "=l"(d) : "l"(a), "l"(b), "l"(c));
    return d;
}
__device__ __forceinline__ ull fadd2(ull a, ull b) {
    ull d;
    asm("add.rn.f32x2 %0, %1, %2;" : "=l"(d) : "l"(a), "l"(b));
    return d;
}

// ---------------- prep1: parallelized softmaxes ----------------
// grid (NG, 17), 256 threads. y in [0,16): B softmax for row c=y of gen g.
// y == 16: A softmax (threads 0..31) + Pi softmax (threads 32,33).
__global__ void htmm_prep1(const float* __restrict__ lA,
                           const float* __restrict__ lB,
                           const float* __restrict__ lPi,
                           const float* __restrict__ lSP) {
    const int g   = blockIdx.x;
    const int y   = blockIdx.y;
    const int tid = threadIdx.x;

    if (y < NC) {
        // ---- B softmax: row c=y over m=256; thread = symbol m ----
        __shared__ float red[16];             // [0..7] max phase, [8..15] sum
        const int wid  = tid >> 5;
        const int lane = tid & 31;
        float v = lB[(((y << 8) + tid) << 3) + g];   // lB[c=y][m=tid][g]

        float m = v;
        #pragma unroll
        for (int o = 16; o; o >>= 1)
            m = fmaxf(m, __shfl_xor_sync(0xffffffffu, m, o));
        if (lane == 0) red[wid] = m;
        __syncthreads();
        float mx = red[0];
        #pragma unroll
        for (int i = 1; i < 8; i++) mx = fmaxf(mx, red[i]);

        float e = expf(v - mx);
        float s = e;
        #pragma unroll
        for (int o = 16; o; o >>= 1)
            s += __shfl_xor_sync(0xffffffffu, s, o);
        if (lane == 0) red[8 + wid] = s;
        __syncthreads();
        float sum = red[8];
        #pragma unroll
        for (int i = 1; i < 8; i++) sum += red[8 + i];

        g_Bn[g][tid][y] = e / sum;
        return;
    }

    // ---- y == 16: A and Pi softmaxes (tiny) ----
    // SP softmax over l (2 values) — redundantly on the active threads
    float a0 = lSP[g], a1 = lSP[8 + g];
    float mxs = fmaxf(a0, a1);
    float e0 = expf(a0 - mxs), e1 = expf(a1 - mxs);
    float inv = 1.0f / (e0 + e1);
    float sp0 = e0 * inv, sp1 = e1 * inv;

    if (tid < 32) {                           // A: (b,l) per thread
        int b = tid >> 1, l = tid & 1;
        float v[NC];
        float m = -3.0e38f;
        #pragma unroll
        for (int a = 0; a < NC; a++) {
            v[a] = lA[((a * 16 + b) * 2 + l) * 8 + g];
            m = fmaxf(m, v[a]);
        }
        float s = 0.0f;
        #pragma unroll
        for (int a = 0; a < NC; a++) { v[a] = expf(v[a] - m); s += v[a]; }
        float scale = (l ? sp1 : sp0) / s;    // fold SP[l] into A
        #pragma unroll
        for (int a = 0; a < NC; a++) g_An[g][l][b][a] = v[a] * scale;
    } else if (tid < 34) {                    // Pi: l per thread
        int l = tid - 32;
        float v[NC];
        float m = -3.0e38f;
        #pragma unroll
        for (int c = 0; c < NC; c++) {
            v[c] = lPi[(c * 2 + l) * 8 + g];
            m = fmaxf(m, v[c]);
        }
        float s = 0.0f;
        #pragma unroll
        for (int c = 0; c < NC; c++) { v[c] = expf(v[c] - m); s += v[c]; }
        float isum = 1.0f / s;
        #pragma unroll
        for (int c = 0; c < NC; c++) g_Pin[g][l][c] = v[c] * isum;
    }
}

// ---------------- prep2: leaf-normalizer table (needs complete g_Bn) --------
// grid NG, 256 threads; thread = symbol m
__global__ void htmm_prep2() {
    const int g = blockIdx.x;
    const int m = threadIdx.x;
    float s0 = 0.0f, s1 = 0.0f;
    #pragma unroll
    for (int c = 0; c < NC; c++) {
        float b = g_Bn[g][m][c];
        s0 = fmaf(g_Pin[g][0][c], b, s0);
        s1 = fmaf(g_Pin[g][1][c], b, s1);
    }
    g_S[g][0][m] = s0;
    g_S[g][1][m] = s1;
}

// ---------------- half-warp (width-16) sum ----------------
__device__ __forceinline__ float hsum16(float v) {
    #pragma unroll
    for (int o = 8; o; o >>= 1) v += __shfl_xor_sync(0xffffffffu, v, o, 16);
    return v;
}

// pair-interleaved contraction: returns sum over both pair lanes of
// sum_b (A0[a,b],A1[a,b]) * (bL[b],bR[b]); cv = 32 floats [b][s]
__device__ __forceinline__ float contract2(const float4* __restrict__ cv,
                                           const ull* __restrict__ rA2) {
    ull a0 = 0ull, a1 = 0ull;
    #pragma unroll
    for (int k = 0; k < 8; k++) {
        F4 q; q.f = cv[k];                    // b = 2k and 2k+1
        a0 = ffma2(rA2[2 * k],     q.u[0], a0);
        a1 = ffma2(rA2[2 * k + 1], q.u[1], a1);
    }
    U2 r; r.u = fadd2(a0, a1);
    return r.f.x + r.f.y;
}

// one level step for one group: node = firstn+ic, children pair ic in `child`.
// Returns the node normalizer nu (1.0 for inactive lanes -> neutral in logs).
__device__ __forceinline__ float level_node(const float* __restrict__ child,
                                            float* __restrict__ parent,
                                            int P, int firstn, int i, bool act,
                                            const int* __restrict__ xs,
                                            const float* __restrict__ Bg,
                                            const ull* __restrict__ rA2,
                                            int lane) {
    int  ic = act ? i : (P - 1);              // clamp: lanes stay convergent
    float t  = contract2((const float4*)(child + (ic << 5)), rA2);
    int   xv = xs[firstn + ic];
    float v  = t * Bg[(xv << 4) + lane];
    float nu = hsum16(v);
    if (act && P > 1)
        parent[((i >> 1) << 5) + 2 * lane + (i & 1)] = __fdividef(v, nu);
    return act ? nu : 1.0f;
}

// group-local level: this group owns CNT consecutive nodes starting at base_i.
// Chunks of <=4 nodes: inside a chunk the 4 LDS/LDG chains are independent
// (MLP~4), and the 4 normalizers are multiplied so __logf runs once per chunk
// (log(prod) == sum(log); products of <=4 normalizers stay in fp32 range).
template <int CNT>
__device__ __forceinline__ void group_level(const float* __restrict__ child,
                                            float* __restrict__ parent,
                                            int P, int firstn, int base_i,
                                            const int* __restrict__ xs,
                                            const float* __restrict__ Bg,
                                            const ull* __restrict__ rA2,
                                            int lane, float& ll) {
    constexpr int CH = (CNT >= 4) ? 4 : CNT;
    for (int c = 0; c < CNT; c += CH) {
        float prod = 1.0f;
        #pragma unroll
        for (int k = 0; k < CH; k++)
            prod *= level_node(child, parent, P, firstn, base_i + c + k, true,
                               xs, Bg, rA2, lane);
        float lg = __logf(prod);              // MUFU issues warp-wide anyway
        if (lane == 0) ll += lg;
    }
}

// ---------------- main kernel: one block per (tree, gen) ----------------
// 128 threads = 8 groups of 16 lanes; half-warp owns one node; lane = state a.
// BLOCKED subtree ownership: group g owns parents [32g,32g+32) at the leaf
// stage, hence nodes [16g,16g+16) at P=128, ... node g at P=8. All level reads
// are group-local (P=8's WRITE crosses only to the sibling half-warp g^1, same
// warp), so the descent 256->8 needs only __syncwarp between levels.
__global__ __launch_bounds__(128, 7)
void htmm_main(const int* __restrict__ x, float* __restrict__ out) {
    // pair-interleaved beta buffers: entry [pair][b][s] at pair*32 + 2b + s
    __shared__ float bufA[256 * NC];          // 16 KB (leaf out, even levels)
    __shared__ float bufB[128 * NC];          // 8 KB  (odd levels)
    __shared__ float stg[8 * 2 * 32];         // leaf staging, double-buffered
    __shared__ int   xs[NODES_PER_TREE];      // 4 KB: this tree's symbols
    __shared__ float wsum[4];

    const int tid  = threadIdx.x;
    const int lane = tid & 15;                // state a
    const int grp  = tid >> 4;                // 0..7
    const int g    = blockIdx.x & 7;
    const int tree = blockIdx.x >> 3;
    const int base = tree * NODES_PER_TREE;
    const unsigned hmask = 0xFFFFu << (tid & 16);   // this half-warp's lanes
    const float* __restrict__ Bg = &g_Bn[g][0][0];
    const float* __restrict__ S0 = &g_S[g][0][0];
    const float* __restrict__ S1 = &g_S[g][1][0];

    // prefetch symbols for this tree (coalesced; 8 rounds of 128)
    #pragma unroll
    for (int j = tid; j < NODES_PER_TREE; j += 128) xs[j] = x[base + j];

    // A' packed per lane: rA2[b] = (A'[a=lane,b,l=0], A'[a=lane,b,l=1])
    ull rA2[NC];
    #pragma unroll
    for (int b = 0; b < NC; b++) {
        U2 t; t.f = make_float2(g_An[g][0][b][lane], g_An[g][1][b][lane]);
        rA2[b] = t.u;
    }
    const float piL = g_Pin[g][0][lane];      // Pi for pos-0 leaf, state lane
    const float piR = g_Pin[g][1][lane];
    __syncthreads();                          // xs ready

    float ll = 0.0f;

    // -------- fused stage: leaves + level-8 parents [32g, 32g+32) --------
    // parent i (node 255+i) has leaf children nodes 511+2i (pos0), 512+2i (pos1)
    {
        int it = 0;
        #pragma unroll 2
        for (int k = 0; k < 32; k++, it ^= 1) {
            int i  = (grp << 5) + k;
            int xL = xs[511 + 2 * i], xR = xs[512 + 2 * i];
            int xp = xs[255 + i];
            float nuL = S0[xL];               // broadcast table hits
            float nuR = S1[xR];
            float vL = __fdividef(piL * Bg[(xL << 4) + lane], nuL);
            float vR = __fdividef(piR * Bg[(xR << 4) + lane], nuR);
            // stage NORMALIZED leaf pair (written+read by THIS half-warp only)
            float* sb = stg + ((grp << 1) + it) * 32;
            *(float2*)(sb + 2 * lane) = make_float2(vL, vR);   // STS.64
            __syncwarp(hmask);                // half-warp-scoped visibility
            float t  = contract2((const float4*)sb, rA2);
            float v  = t * Bg[(xp << 4) + lane];
            float nu = hsum16(v);
            bufA[((i >> 1) << 5) + 2 * lane + (i & 1)] = __fdividef(v, nu);
            float lg = __logf(nuL * nuR * nu);
            if (lane == 0) ll += lg;
        }
    }
    __syncwarp();

    // -------- group-local descent: P = 128, 64, 32, 16, 8 --------
    group_level<16>(bufA, bufB, 128, 127, grp << 4, xs, Bg, rA2, lane, ll);
    __syncwarp();
    group_level< 8>(bufB, bufA,  64,  63, grp << 3, xs, Bg, rA2, lane, ll);
    __syncwarp();
    group_level< 4>(bufA, bufB,  32,  31, grp << 2, xs, Bg, rA2, lane, ll);
    __syncwarp();
    group_level< 2>(bufB, bufA,  16,  15, grp << 1, xs, Bg, rA2, lane, ll);
    __syncwarp();
    group_level< 1>(bufA, bufB,   8,   7, grp,      xs, Bg, rA2, lane, ll);
    __syncthreads();   // P=4 (warp 0) consumes pairs written by warps 0..3

    // -------- warp-collapsed top levels: P = 4, 2, 1 on warp 0 only --------
    // current child buffer is bufB
    if (tid < 32) {                           // groups 0,1
        // P = 4 (nodes 3..6): two iterations over groups 0,1
        float n0 = level_node(bufB, bufA, 4, 3, grp,     true, xs, Bg, rA2, lane);
        float n1 = level_node(bufB, bufA, 4, 3, grp + 2, true, xs, Bg, rA2, lane);
        __syncwarp();
        // P = 2 (nodes 1,2): groups 0,1 both active
        float n2 = level_node(bufA, bufB, 2, 1, grp, true, xs, Bg, rA2, lane);
        __syncwarp();
        // P = 1 (root, node 0): group 0 active, group 1 clamped
        float n3 = level_node(bufB, bufA, 1, 0, grp, grp == 0, xs, Bg, rA2, lane);
        float lg = __logf(n0 * n1 * n2 * n3);
        if (lane == 0) ll += lg;
    }

    // -------- block reduction of ll --------
    #pragma unroll
    for (int o = 16; o; o >>= 1) ll += __shfl_xor_sync(0xffffffffu, ll, o);
    if ((tid & 31) == 0) wsum[tid >> 5] = ll;
    __syncthreads();
    if (tid == 0)
        out[blockIdx.x] = wsum[0] + wsum[1] + wsum[2] + wsum[3];  // out[tree*8+g]
}

// ---------------- launch ----------------
extern "C" void kernel_launch(void* const* d_in, const int* in_sizes, int n_in,
                              void* d_out, int out_size) {
    const float* lA  = (const float*)d_in[0];   // lambda_A  (C,C,L,G)
    const float* lB  = (const float*)d_in[1];   // lambda_B  (C,M,G)
    const float* lPi = (const float*)d_in[2];   // lambda_Pi (C,L,G)
    const float* lSP = (const float*)d_in[3];   // lambda_SP (L,G)
    const int*   x   = (const int*)  d_in[4];   // x (N,)
    float* out = (float*)d_out;                 // (N_TREES, N_GEN) = 1024 floats

    // occupancy insurance: request max shared-memory carveout so 7 blocks/SM
    // (7 x ~30.2 KB = 212 KB) actually fit; without this a conservative
    // driver carveout could silently drop occupancy to ~3 blocks/SM.
    cudaFuncSetAttribute(htmm_main,
                         cudaFuncAttributePreferredSharedMemoryCarveout, 100);

    dim3 grid1(NG, NC + 1);                     // 8 gens x (16 B-rows + A/Pi)
    htmm_prep1<<<grid1, 256>>>(lA, lB, lPi, lSP);
    htmm_prep2<<<NG, 256>>>();                  // S table (needs complete g_Bn)
    htmm_main<<<N_TREES * NG, 128>>>(x, out);
}